// round 9
// baseline (speedup 1.0000x reference)
#include <cuda_runtime.h>
#include <cstdint>

// Problem constants (from reference): V=100000 vocab (<2^17), D=128 dim, R=20000 (<2^15)
#define VOCAB 100000
#define DIM4  32   // 128 floats = 32 float4
#define RES_BIT (1u << 30)
#define BATCH 4    // tokens per copy stage (independent LDG.128 in flight)

// Scratch: vocab -> packed ((v+1)<<15 | row). Self-validating: gather checks
// the tag (v+1) so no -1 fill pass and no third validation load are needed.
// Stale/zero-init entries fail the tag check deterministically.
__device__ unsigned g_remap[VOCAB];

__global__ void scatter_remap_kernel(const int* __restrict__ ridx, int R) {
    int i = blockIdx.x * blockDim.x + threadIdx.x;
    if (i < R) {
        unsigned v = (unsigned)ridx[i];
        g_remap[v] = ((v + 1u) << 15) | (unsigned)i;
    }
}

// Each warp owns 32 tokens.
// Phase 1: lane t resolves token t's chain with TWO dependent loads
//          (x -> packed remap word), parallel across 32 lanes.
// Phase 2: copy loop, BATCH tokens per stage (BATCH independent LDG.128
//          in flight), each lane moves one float4 per token. Streaming
//          stores keep the embedding tables L2-resident.
__global__ __launch_bounds__(256)
void gather_kernel(const int* __restrict__ x,
                   const float4* __restrict__ pre,   // [V, 32] float4
                   const float4* __restrict__ res,   // [R, 32] float4
                   float4* __restrict__ out,         // [n_tok, 32] float4
                   int n_tok) {
    int warp = (blockIdx.x * blockDim.x + threadIdx.x) >> 5;
    int lane = threadIdx.x & 31;
    long long base = (long long)warp * 32;
    if (base >= n_tok) return;
    bool full = (base + 32 <= n_tok);

    // ---- Phase 1: per-lane index resolution (2 dependent loads) ----
    long long mytok = base + lane;
    unsigned v = (mytok < n_tok) ? (unsigned)__ldg(x + mytok) : 0u;
    unsigned m = g_remap[v];
    bool use_res = ((m >> 15) == v + 1u);           // tag match => residual row
    // pack for shuffle: bit30 = residual flag, low bits = row index
    unsigned packed = use_res ? ((m & 0x7FFFu) | RES_BIT) : v;

    if (full) {
        // Fast path: no bounds checks, BATCH-deep load pipelining.
        #pragma unroll
        for (int t0 = 0; t0 < 32; t0 += BATCH) {
            float4 val[BATCH];
            #pragma unroll
            for (int k = 0; k < BATCH; k++) {
                unsigned p = __shfl_sync(0xFFFFFFFFu, packed, t0 + k);
                const float4* srow = (p & RES_BIT)
                                   ? (res + (long long)(p & ~RES_BIT) * DIM4)
                                   : (pre + (long long)p * DIM4);
                val[k] = __ldg(srow + lane);
            }
            #pragma unroll
            for (int k = 0; k < BATCH; k++)
                __stcs(out + (base + t0 + k) * DIM4 + lane, val[k]);
        }
    } else {
        // Tail warp (not hit for n_tok % 32 == 0, kept for generality).
        for (int t = 0; t < 32; t++) {
            long long tok = base + t;
            if (tok >= n_tok) break;
            unsigned p = __shfl_sync(0xFFFFFFFFu, packed, t);
            const float4* srow = (p & RES_BIT)
                               ? (res + (long long)(p & ~RES_BIT) * DIM4)
                               : (pre + (long long)p * DIM4);
            __stcs(out + tok * DIM4 + lane, __ldg(srow + lane));
        }
    }
}

extern "C" void kernel_launch(void* const* d_in, const int* in_sizes, int n_in,
                              void* d_out, int out_size) {
    // Input order per reference setup_inputs():
    //   0: x                    [B*S]   int32
    //   1: residual_index       [R]     int32
    //   2: pretrained_embedding [V*D]   float32
    //   3: residual_embedding   [R*D]   float32
    const int*    x    = (const int*)d_in[0];
    const int*    ridx = (const int*)d_in[1];
    const float4* pre  = (const float4*)d_in[2];
    const float4* res  = (const float4*)d_in[3];
    float4*       out  = (float4*)d_out;

    const int n_tok = in_sizes[0];          // B*S = 262144
    const int R     = in_sizes[1];          // 20000

    scatter_remap_kernel<<<(R + 127) / 128, 128>>>(ridx, R);

    const long long n_warps = ((long long)n_tok + 31) / 32;   // 32 tokens per warp
    const long long total_threads = n_warps * 32;
    const int block = 256;
    const int grid  = (int)((total_threads + block - 1) / block);
    gather_kernel<<<grid, block>>>(x, pre, res, out, n_tok);
}

// round 10
// speedup vs baseline: 1.2992x; 1.2992x over previous
#include <cuda_runtime.h>
#include <cstdint>

// Problem constants (from reference): V=100000 vocab, D=128 dim
#define VOCAB 100000
#define DIM4  32   // 128 floats = 32 float4
#define RES_BIT (1u << 30)
#define TPW   16   // tokens per warp (grid sizing: 2048 CTAs for occupancy)
#define BATCH 4    // tokens per copy stage (independent LDG.128 in flight)

// Scratch: vocab -> candidate residual row. Validated in gather via
// ridx[row] == v, so no -1 fill pass is needed.
__device__ int g_remap[VOCAB];

__global__ void scatter_remap_kernel(const int* __restrict__ ridx, int R) {
    int i = blockIdx.x * blockDim.x + threadIdx.x;
    if (i < R) {
        g_remap[ridx[i]] = i;
    }
}

// Each warp owns TPW=16 tokens.
// Phase 1: lanes 0..15 resolve one token each (3 coalesced LDGs, MLP=16/warp).
// Phase 2: copy loop, BATCH tokens per stage (BATCH independent LDG.128 in
//          flight), each lane moves one float4 per token. Streaming stores
//          keep the embedding tables L2-resident (reads are 100% L2-hit).
// __launch_bounds__(256, 8) pins regs <= 32 so 8 CTAs reside per SM.
__global__ __launch_bounds__(256, 8)
void gather_kernel(const int* __restrict__ x,
                   const int* __restrict__ ridx,     // [R] sorted, L2-hot
                   const float4* __restrict__ pre,   // [V, 32] float4
                   const float4* __restrict__ res,   // [R, 32] float4
                   float4* __restrict__ out,         // [n_tok, 32] float4
                   int n_tok, int R) {
    int warp = (blockIdx.x * blockDim.x + threadIdx.x) >> 5;
    int lane = threadIdx.x & 31;
    long long base = (long long)warp * TPW;
    if (base >= n_tok) return;
    bool full = (base + TPW <= n_tok);

    // ---- Phase 1: lanes 0..TPW-1 resolve one token each ----
    long long mytok = base + (lane & (TPW - 1));
    int v = (mytok < n_tok) ? __ldg(x + mytok) : 0;
    int r = g_remap[v];
    bool use_res = (r >= 0) && (r < R) && (__ldg(ridx + r) == v);
    // pack: bit30 = residual flag, low bits = row index (fits: V < 2^17)
    unsigned packed = use_res ? ((unsigned)r | RES_BIT) : (unsigned)v;

    if (full) {
        // Fast path: no bounds checks, BATCH-deep load pipelining.
        #pragma unroll
        for (int t0 = 0; t0 < TPW; t0 += BATCH) {
            float4 val[BATCH];
            #pragma unroll
            for (int k = 0; k < BATCH; k++) {
                unsigned p = __shfl_sync(0xFFFFFFFFu, packed, t0 + k);
                const float4* srow = (p & RES_BIT)
                                   ? (res + (long long)(p & ~RES_BIT) * DIM4)
                                   : (pre + (long long)p * DIM4);
                val[k] = __ldg(srow + lane);
            }
            #pragma unroll
            for (int k = 0; k < BATCH; k++)
                __stcs(out + (base + t0 + k) * DIM4 + lane, val[k]);
        }
    } else {
        // Tail warp (not hit for n_tok % TPW == 0, kept for generality).
        for (int t = 0; t < TPW; t++) {
            long long tok = base + t;
            if (tok >= n_tok) break;
            unsigned p = __shfl_sync(0xFFFFFFFFu, packed, t);
            const float4* srow = (p & RES_BIT)
                               ? (res + (long long)(p & ~RES_BIT) * DIM4)
                               : (pre + (long long)p * DIM4);
            __stcs(out + tok * DIM4 + lane, __ldg(srow + lane));
        }
    }
}

extern "C" void kernel_launch(void* const* d_in, const int* in_sizes, int n_in,
                              void* d_out, int out_size) {
    // Input order per reference setup_inputs():
    //   0: x                    [B*S]   int32
    //   1: residual_index       [R]     int32
    //   2: pretrained_embedding [V*D]   float32
    //   3: residual_embedding   [R*D]   float32
    const int*    x    = (const int*)d_in[0];
    const int*    ridx = (const int*)d_in[1];
    const float4* pre  = (const float4*)d_in[2];
    const float4* res  = (const float4*)d_in[3];
    float4*       out  = (float4*)d_out;

    const int n_tok = in_sizes[0];          // B*S = 262144
    const int R     = in_sizes[1];          // 20000

    scatter_remap_kernel<<<(R + 127) / 128, 128>>>(ridx, R);

    const long long n_warps = ((long long)n_tok + TPW - 1) / TPW;
    const long long total_threads = n_warps * 32;
    const int block = 256;
    const int grid  = (int)((total_threads + block - 1) / block);
    gather_kernel<<<grid, block>>>(x, ridx, pre, res, out, n_tok, R);
}